// round 1
// baseline (speedup 1.0000x reference)
#include <cuda_runtime.h>
#include <math.h>

// Problem shapes (fixed by dataset)
#define SS 2048
#define BB 32
#define HH 1024

// K_A tiling: split the o (output/contraction) dimension into NOB chunks of OC
#define OC  64
#define NOB (HH / OC)   // 16

// Scratch (static __device__ — no allocations allowed)
__device__ float g_u_part[NOB][BB * HH];  // 2 MB
__device__ float g_u[BB * HH];            // 128 KB
__device__ float g_scores[BB * SS];       // 256 KB

// ---------------------------------------------------------------------------
// K_A: u_part[ob][b][h] = sum_{o in chunk ob} hidden[b,o] * W[o,h]
// grid (HH/128, NOB), block 128. W element read exactly once across the grid.
// ---------------------------------------------------------------------------
__global__ void __launch_bounds__(128) k_upart(const float* __restrict__ hidden,
                                               const float* __restrict__ W) {
    __shared__ float hs[OC * BB];  // hs[o*BB + b] = hidden[b, o0+o]
    const int h0 = blockIdx.x * 128;
    const int o0 = blockIdx.y * OC;

    for (int i = threadIdx.x; i < OC * BB; i += 128) {
        int o = i >> 5;       // /32
        int b = i & 31;
        hs[i] = hidden[b * HH + o0 + o];
    }
    __syncthreads();

    const int h = h0 + threadIdx.x;
    float acc[BB];
#pragma unroll
    for (int b = 0; b < BB; ++b) acc[b] = 0.f;

    for (int o = 0; o < OC; ++o) {
        float w = W[(size_t)(o0 + o) * HH + h];
#pragma unroll
        for (int b = 0; b < BB; ++b) acc[b] = fmaf(hs[o * BB + b], w, acc[b]);
    }

#pragma unroll
    for (int b = 0; b < BB; ++b) g_u_part[blockIdx.y][b * HH + h] = acc[b];
}

// ---------------------------------------------------------------------------
// K_B: u[i] = sum over the NOB partials. grid 128, block 256.
// ---------------------------------------------------------------------------
__global__ void __launch_bounds__(256) k_ureduce() {
    int i = blockIdx.x * 256 + threadIdx.x;  // i < BB*HH = 32768
    float s = 0.f;
#pragma unroll
    for (int p = 0; p < NOB; ++p) s += g_u_part[p][i];
    g_u[i] = s;
}

// ---------------------------------------------------------------------------
// K_C (dominant, HBM-bound): scores[b,s] = u[b] . enc[s,b,:]
// grid (SS/32, BB), block 256 (8 warps). Each warp handles 4 consecutive s.
// u[b] cached in smem (4 KB). enc rows are contiguous 4 KB -> float4 coalesced.
// ---------------------------------------------------------------------------
#define SPW 4  // s-rows per warp

__global__ void __launch_bounds__(256) k_scores(const float* __restrict__ enc,
                                                float* __restrict__ scores) {
    const int b = blockIdx.y;
    __shared__ float4 u_sm[HH / 4];  // 256 float4

    const float4* ub = reinterpret_cast<const float4*>(g_u + b * HH);
    for (int i = threadIdx.x; i < HH / 4; i += 256) u_sm[i] = ub[i];
    __syncthreads();

    const int warp = threadIdx.x >> 5;
    const int lane = threadIdx.x & 31;
    const int s_base = (blockIdx.x * 8 + warp) * SPW;

#pragma unroll
    for (int r = 0; r < SPW; ++r) {
        const int s = s_base + r;
        const float4* row =
            reinterpret_cast<const float4*>(enc + ((size_t)s * BB + b) * HH);
        float acc = 0.f;
#pragma unroll
        for (int c = 0; c < 8; ++c) {
            float4 e = row[c * 32 + lane];
            float4 u = u_sm[c * 32 + lane];
            acc += e.x * u.x + e.y * u.y + e.z * u.z + e.w * u.w;
        }
#pragma unroll
        for (int off = 16; off; off >>= 1)
            acc += __shfl_xor_sync(0xFFFFFFFFu, acc, off);
        if (lane == 0) scores[b * SS + s] = acc;
    }
}

// ---------------------------------------------------------------------------
// K_D: per-b softmax over s (row length 2048). grid BB, block 256.
// Writes d_out directly ([B,1,S] is contiguous [B*S]).
// ---------------------------------------------------------------------------
__global__ void __launch_bounds__(256) k_softmax(float* __restrict__ out) {
    const int b = blockIdx.x;
    const int t = threadIdx.x;
    __shared__ float red[8];

    float v[8];
    float m = -1e30f;
#pragma unroll
    for (int i = 0; i < 8; ++i) {
        v[i] = g_scores[b * SS + t + i * 256];
        m = fmaxf(m, v[i]);
    }
#pragma unroll
    for (int off = 16; off; off >>= 1)
        m = fmaxf(m, __shfl_xor_sync(0xFFFFFFFFu, m, off));
    if ((t & 31) == 0) red[t >> 5] = m;
    __syncthreads();
    float bm = red[0];
#pragma unroll
    for (int w = 1; w < 8; ++w) bm = fmaxf(bm, red[w]);
    __syncthreads();  // before reusing red[]

    float sum = 0.f;
#pragma unroll
    for (int i = 0; i < 8; ++i) {
        v[i] = expf(v[i] - bm);
        sum += v[i];
    }
#pragma unroll
    for (int off = 16; off; off >>= 1)
        sum += __shfl_xor_sync(0xFFFFFFFFu, sum, off);
    if ((t & 31) == 0) red[t >> 5] = sum;
    __syncthreads();
    float tot = red[0];
#pragma unroll
    for (int w = 1; w < 8; ++w) tot += red[w];

    float inv = 1.f / tot;
#pragma unroll
    for (int i = 0; i < 8; ++i) out[b * SS + t + i * 256] = v[i] * inv;
}

// ---------------------------------------------------------------------------
// Inputs (metadata order): hidden [B,H], encoder_outputs [S,B,H], W [H,H], b [H]
// The bias input is mathematically irrelevant (softmax shift invariance).
// ---------------------------------------------------------------------------
extern "C" void kernel_launch(void* const* d_in, const int* in_sizes, int n_in,
                              void* d_out, int out_size) {
    const float* hidden = (const float*)d_in[0];
    const float* enc    = (const float*)d_in[1];
    const float* W      = (const float*)d_in[2];
    float* out          = (float*)d_out;

    k_upart<<<dim3(HH / 128, NOB), 128>>>(hidden, W);
    k_ureduce<<<(BB * HH) / 256, 256>>>();

    float* scores_ptr;
    cudaGetSymbolAddress((void**)&scores_ptr, g_scores);
    k_scores<<<dim3(SS / (8 * SPW), BB), 256>>>(enc, scores_ptr);
    k_softmax<<<BB, 256>>>(out);
}